// round 4
// baseline (speedup 1.0000x reference)
#include <cuda_runtime.h>
#include <cuda_bf16.h>
#include <math.h>

// Problem constants (fixed by setup_inputs)
#define Bv    32
#define Cc    256
#define Nn    64
#define NNv   4096
#define Sv    64
#define Pv    2080          // triu(64x64) count
#define TPn   256           // positions per K2 block
#define NT2   9             // ceil(2080/256)
#define NROWS (Bv*NT2)      // 288 partial rows
#define NEGW  72            // words per sentence for neg bitmask (9 tiles * 8)

typedef unsigned long long u64;
union F2 { u64 u; float2 f; };

__device__ __forceinline__ void fma2(u64 &acc, u64 a, u64 b) {
    asm("fma.rn.f32x2 %0, %1, %2, %0;" : "+l"(acc) : "l"(a), "l"(b));
}
__device__ __forceinline__ u64 dup2(float v) {
    u64 r; asm("mov.b64 %0, {%1,%1};" : "=l"(r) : "f"(v)); return r;
}
__device__ __forceinline__ u64 pack2(float a, float b) {
    u64 r; asm("mov.b64 %0, {%1,%2};" : "=l"(r) : "f"(a), "f"(b)); return r;
}

// triu row from compacted index p: largest r with r*(129-r)/2 <= p
__device__ __forceinline__ int rowof(int p) {
    int r = (int)((129.0f - sqrtf(16641.0f - 8.0f * (float)p)) * 0.5f);
    if (r < 0) r = 0; if (r > 63) r = 63;
    while (r < 63 && (r + 1) * (129 - (r + 1)) / 2 <= p) r++;
    while (r > 0 && r * (129 - r) / 2 > p) r--;
    return r;
}

// -------- device scratch (no allocations allowed) --------
__device__ float    g_sf[Cc * Sv];      // [c][s] normalized sentence feats
__device__ int      g_scatter[Sv];
__device__ int      g_toppos[Sv];       // argmax-iou flat position per sentence
__device__ unsigned g_negw[Sv * NEGW];  // iou>0.5 bits over compacted positions
__device__ float    g_part[NROWS * Sv]; // per-block partial neg sums
__device__ float    g_A[Sv * Sv];       // inter-video score matrix A[s][t]

// ============================================================
// K1a (pos 1): normalized sentence feats [c][s] + scatter idx.
// ============================================================
__global__ void k1a_setup(const float* __restrict__ sents,
                          const int*   __restrict__ num_targets) {
    int tid = threadIdx.x;               // 128 threads
    int w = tid >> 5, lane = tid & 31;

    if (tid == 0) {
        int s = 0;
        for (int b = 0; b < Bv && s < Sv; b++) {
            int n = num_targets[b];
            for (int k = 0; k < n && s < Sv; k++) g_scatter[s++] = b;
        }
    }
    for (int s = w; s < Sv; s += 4) {
        float vs[8]; float ss = 0.f;
        #pragma unroll
        for (int k = 0; k < 8; k++) {
            float v = sents[s * Cc + lane + k * 32];
            vs[k] = v; ss += v * v;
        }
        #pragma unroll
        for (int o = 16; o; o >>= 1) ss += __shfl_xor_sync(0xffffffffu, ss, o);
        float rn = 1.f / fmaxf(sqrtf(ss), 1e-12f);
        #pragma unroll
        for (int k = 0; k < 8; k++)
            g_sf[(lane + k * 32) * Sv + s] = vs[k] * rn;
    }
}

// ============================================================
// K1b (pos 2): neg-mask bits via ballot (cp-ordered).
// ============================================================
__global__ void k1b_negbits(const float* __restrict__ iou) {
    int s = blockIdx.x;
    int tid = threadIdx.x;      // 128
    int w = tid >> 5, lane = tid & 31;
    #pragma unroll
    for (int k = 0; k < 18; k++) {
        int cp = k * 128 + tid;
        bool bit = false;
        if (cp < Pv) {
            int r = rowof(cp);
            int f = r * Nn + r + (cp - r * (129 - r) / 2);
            bit = iou[s * NNv + f] > 0.5f;
        }
        unsigned word = __ballot_sync(0xffffffffu, bit);
        if (lane == 0) g_negw[s * NEGW + 4 * k + w] = word;
    }
}

// ============================================================
// K1c (pos 3): per-sentence iou argmax over triu positions.
// ============================================================
__global__ void k1c_argmax(const float* __restrict__ iou) {
    int s = blockIdx.x;
    int t = threadIdx.x;   // 128
    __shared__ float sv[128];
    __shared__ int   sf[128];

    float bv = -1e30f; int bf = 0x3fffffff;
    #pragma unroll 4
    for (int f = t; f < NNv; f += 128) {
        int r = f >> 6, c = f & 63;
        if (c >= r) {
            float v = iou[s * NNv + f];
            if (v > bv || (v == bv && f < bf)) { bv = v; bf = f; }
        }
    }
    sv[t] = bv; sf[t] = bf;
    __syncthreads();
    for (int o = 64; o; o >>= 1) {
        if (t < o) {
            float ov = sv[t + o]; int of = sf[t + o];
            if (ov > sv[t] || (ov == sv[t] && of < sf[t])) { sv[t] = ov; sf[t] = of; }
        }
        __syncthreads();
    }
    if (t == 0) g_toppos[s] = sf[0];
}

// ============================================================
// K2 (pos 4): fused GEMM + norms + exp/neg-mask partials + A scatter.
//   256 threads, 256-pos tile, thread tile 8 pos x 8 sentences.
//   f32x2 accumulator pairs span SENTENCES (un-dup smem operand);
//   video dup pair built register-side (mov.b64 {v,v}).
//   Sentence matrix (64KB) resident in smem for the whole block.
// ============================================================
// dynamic smem layout (bytes):
#define SM_SF   0                       // [256][64] f   = 65536
#define SM_V    65536                   // [2][8][256] f = 16384
#define SM_RN   (65536+16384)           // [256] f       = 1024
#define SM_NEG  (SM_RN+1024)            // [64][8] u     = 2048
#define SM_PART (SM_NEG+2048)           // [64][32] f    = 8192
#define SM_SCAT (SM_PART+8192)          // [64] i        = 256
#define SM_TOP  (SM_SCAT+256)           // [64] i        = 256
#define SM_LJ   (SM_TOP+256)            // [64] i        = 256
#define SM_LP   (SM_LJ+256)             // [64] i        = 256
#define SM_CNT  (SM_LP+256)             // [1] i
#define SM_TOTAL (SM_CNT+16)

__global__ void __launch_bounds__(256, 2)
k2_gemm(const float* __restrict__ V) {
    extern __shared__ __align__(16) char smraw[];
    float*    s_sf   = (float*)(smraw + SM_SF);
    float*    s_v    = (float*)(smraw + SM_V);
    float*    s_rn   = (float*)(smraw + SM_RN);
    unsigned* s_neg  = (unsigned*)(smraw + SM_NEG);
    float*    s_part = (float*)(smraw + SM_PART);
    int*      s_scat = (int*)(smraw + SM_SCAT);
    int*      s_top  = (int*)(smraw + SM_TOP);
    int*      s_lj   = (int*)(smraw + SM_LJ);
    int*      s_lp   = (int*)(smraw + SM_LP);
    int*      s_cnt  = (int*)(smraw + SM_CNT);

    int tile = blockIdx.x;
    int b    = blockIdx.y;
    int p0   = tile * TPn;

    int tid = threadIdx.x;       // 256
    int tx = tid & 31;           // pos group (8 pos each)  -> 256 pos
    int ty = tid >> 5;           // sentence group (8 s each) -> 64 s

    // per-thread load position (flat index)
    int p = p0 + tid;
    int ldf = -1;
    if (p < Pv) {
        int r = rowof(p);
        ldf = r * Nn + r + (p - r * (129 - r) / 2);
    }

    // ---- block fills ----
    for (int i = tid; i < (Cc * Sv) / 4; i += 256)
        ((float4*)s_sf)[i] = ((const float4*)g_sf)[i];
    for (int i = tid; i < Sv * 8; i += 256) {
        int s = i >> 3, w = i & 7;
        s_neg[i] = g_negw[s * NEGW + tile * 8 + w];
    }
    if (tid < Sv) { s_scat[tid] = g_scatter[tid]; s_top[tid] = g_toppos[tid]; }
    if (tid == 0) *s_cnt = 0;

    const float* Vb = V + (size_t)b * Cc * NNv;

    // prefetch chunk 0 (8 channels)
    float pv[8];
    #pragma unroll
    for (int k = 0; k < 8; k++)
        pv[k] = (ldf >= 0) ? Vb[k * NNv + ldf] : 0.f;

    __syncthreads();   // fills visible

    // toplist scan (hidden under prefetch latency)
    if (ldf >= 0) {
        #pragma unroll 8
        for (int j = 0; j < Sv; j++) {
            if (s_scat[j] == b && s_top[j] == ldf) {
                int idx = atomicAdd(s_cnt, 1);
                s_lj[idx] = j; s_lp[idx] = tid;
            }
        }
    }

    u64 acc[4][8];     // [sentence-pair][pos]
    #pragma unroll
    for (int sp = 0; sp < 4; sp++)
        #pragma unroll
        for (int j = 0; j < 8; j++) acc[sp][j] = 0ull;
    u64 nacc[4] = {0ull, 0ull, 0ull, 0ull};  // pos-pair norms (warp 0)

    for (int ci = 0; ci < Cc / 8; ci++) {
        int cur = ci & 1;
        #pragma unroll
        for (int k = 0; k < 8; k++)
            s_v[(cur * 8 + k) * TPn + tid] = pv[k];
        __syncthreads();
        if (ci + 1 < Cc / 8) {
            #pragma unroll
            for (int k = 0; k < 8; k++)
                pv[k] = (ldf >= 0) ? Vb[((ci + 1) * 8 + k) * NNv + ldf] : 0.f;
        }
        #pragma unroll
        for (int cc = 0; cc < 8; cc++) {
            const float* vrow = &s_v[(cur * 8 + cc) * TPn + tx * 8];
            float4 f4a = *(const float4*)(vrow);
            float4 f4b = *(const float4*)(vrow + 4);
            const float* srow = &s_sf[(ci * 8 + cc) * Sv + ty * 8];
            ulonglong2 sA = *(const ulonglong2*)(srow);
            ulonglong2 sB = *(const ulonglong2*)(srow + 4);
            u64 sd0 = sA.x, sd1 = sA.y, sd2 = sB.x, sd3 = sB.y;
            float vv[8] = {f4a.x, f4a.y, f4a.z, f4a.w, f4b.x, f4b.y, f4b.z, f4b.w};
            #pragma unroll
            for (int j = 0; j < 8; j++) {
                u64 vd = dup2(vv[j]);
                fma2(acc[0][j], sd0, vd);
                fma2(acc[1][j], sd1, vd);
                fma2(acc[2][j], sd2, vd);
                fma2(acc[3][j], sd3, vd);
            }
            if (ty == 0) {   // column norms, warp 0 only
                u64 q0 = pack2(vv[0], vv[1]); fma2(nacc[0], q0, q0);
                u64 q1 = pack2(vv[2], vv[3]); fma2(nacc[1], q1, q1);
                u64 q2 = pack2(vv[4], vv[5]); fma2(nacc[2], q2, q2);
                u64 q3 = pack2(vv[6], vv[7]); fma2(nacc[3], q3, q3);
            }
        }
    }

    if (ty == 0) {
        #pragma unroll
        for (int k = 0; k < 4; k++) {
            F2 u; u.u = nacc[k];
            s_rn[tx * 8 + 2 * k]     = 1.f / fmaxf(sqrtf(u.f.x), 1e-12f);
            s_rn[tx * 8 + 2 * k + 1] = 1.f / fmaxf(sqrtf(u.f.y), 1e-12f);
        }
    }
    __syncthreads();

    float rn[8];
    #pragma unroll
    for (int j = 0; j < 8; j++) rn[j] = s_rn[tx * 8 + j];
    int cnt = *s_cnt;

    // epilogue: masked exp partials (8 sentences per thread)
    #pragma unroll
    for (int sp = 0; sp < 4; sp++) {
        #pragma unroll
        for (int h = 0; h < 2; h++) {
            int s = ty * 8 + 2 * sp + h;
            bool samevid = (s_scat[s] == b);
            unsigned negw = s_neg[s * 8 + (tx >> 2)];
            float part = 0.f;
            #pragma unroll
            for (int j = 0; j < 8; j++) {
                F2 u; u.u = acc[sp][j];
                float sc = (h ? u.f.y : u.f.x) * rn[j];
                int lpj = tx * 8 + j;
                bool pos = samevid && ((negw >> (lpj & 31)) & 1u);
                if ((p0 + lpj) < Pv && !pos)
                    part += __expf(sc * 10.0f);   // exp(score / 0.1)
            }
            s_part[s * 32 + tx] = part;
        }
    }

    // inter-video score scatter: A[j][t] for tops owned by this block
    for (int i = 0; i < cnt; i++) {
        int l = s_lp[i];
        if ((l >> 3) == tx) {
            int jj = l & 7;
            #pragma unroll
            for (int sp = 0; sp < 4; sp++) {
                F2 u; u.u = acc[sp][jj];
                g_A[s_lj[i] * Sv + ty * 8 + 2 * sp]     = u.f.x * rn[jj];
                g_A[s_lj[i] * Sv + ty * 8 + 2 * sp + 1] = u.f.y * rn[jj];
            }
        }
    }
    __syncthreads();

    if (tid < Sv) {
        float sum = 0.f;
        #pragma unroll
        for (int k = 0; k < 32; k++) sum += s_part[tid * 32 + k];
        g_part[((size_t)b * NT2 + tile) * Sv + tid] = sum;
    }
}

// ============================================================
// K5 (pos 5): final reductions -> two scalar losses. 1024 thr.
// ============================================================
__global__ void k5_final(float* __restrict__ out) {
    __shared__ float sh_lq[64];
    __shared__ float sh_lv[64];
    __shared__ float sh[64];
    int t = threadIdx.x;     // 1024
    int s = t >> 4, k = t & 15;

    // inter-query neg sums: 16 threads per sentence over 288 rows
    float ns = 0.f;
    #pragma unroll 6
    for (int i = k; i < NROWS; i += 16)
        ns += g_part[(size_t)i * Sv + s];
    ns += __shfl_xor_sync(0xffffffffu, ns, 1);
    ns += __shfl_xor_sync(0xffffffffu, ns, 2);
    ns += __shfl_xor_sync(0xffffffffu, ns, 4);
    ns += __shfl_xor_sync(0xffffffffu, ns, 8);
    if (k == 0) {
        float ps = g_A[s * Sv + s];
        float pe = __expf(ps * 10.0f);
        sh_lq[s] = logf(pe + ns) - ps * 10.0f;
    }

    // inter-video: 16 threads per sentence over 64 columns of A
    float nsv = 0.f;
    #pragma unroll
    for (int q = 0; q < 4; q++) {
        int u2 = k * 4 + q;
        if (u2 != s) nsv += __expf(g_A[s * Sv + u2] * 10.0f);
    }
    nsv += __shfl_xor_sync(0xffffffffu, nsv, 1);
    nsv += __shfl_xor_sync(0xffffffffu, nsv, 2);
    nsv += __shfl_xor_sync(0xffffffffu, nsv, 4);
    nsv += __shfl_xor_sync(0xffffffffu, nsv, 8);
    if (k == 0) {
        float ps = g_A[s * Sv + s];
        float pe = __expf(ps * 10.0f);
        sh_lv[s] = logf(pe + nsv) - ps * 10.0f;
    }
    __syncthreads();

    if (t < 64) sh[t] = sh_lq[t];
    __syncthreads();
    #pragma unroll
    for (int o = 32; o; o >>= 1) {
        if (t < o) sh[t] += sh[t + o];
        __syncthreads();
    }
    if (t == 0) out[1] = sh[0] / 64.0f;
    __syncthreads();

    if (t < 64) sh[t] = sh_lv[t];
    __syncthreads();
    #pragma unroll
    for (int o = 32; o; o >>= 1) {
        if (t < o) sh[t] += sh[t + o];
        __syncthreads();
    }
    if (t == 0) out[0] = sh[0] / 64.0f;
}

// ============================================================
extern "C" void kernel_launch(void* const* d_in, const int* in_sizes, int n_in,
                              void* d_out, int out_size) {
    const float* video = (const float*)d_in[0];   // [32,256,64,64]
    const float* sents = (const float*)d_in[1];   // [64,256]
    const int*   ntg   = (const int*)  d_in[2];   // [32]
    const float* iou   = (const float*)d_in[3];   // [64,64,64]
    // d_in[4] = mask2d (structural triu constant; handled analytically)

    static int smem_set = 0;
    if (!smem_set) {
        cudaFuncSetAttribute(k2_gemm, cudaFuncAttributeMaxDynamicSharedMemorySize,
                             SM_TOTAL);
        smem_set = 1;
    }

    k1a_setup  <<<1, 128>>>(sents, ntg);                     // pos 1
    k1b_negbits<<<Sv, 128>>>(iou);                           // pos 2
    k1c_argmax <<<Sv, 128>>>(iou);                           // pos 3
    k2_gemm    <<<dim3(NT2, Bv), 256, SM_TOTAL>>>(video);    // pos 4 (profiled)
    k5_final   <<<1, 1024>>>((float*)d_out);                 // pos 5
}

// round 6
// speedup vs baseline: 2.2347x; 2.2347x over previous
#include <cuda_runtime.h>
#include <cuda_bf16.h>
#include <math.h>

// Problem constants (fixed by setup_inputs)
#define Bv    32
#define Cc    256
#define Nn    64
#define NNv   4096
#define Sv    64
#define Pv    2080          // triu(64x64) count
#define TP    128           // positions per K2 tile
#define NTIL  17            // ceil(2080/128)
#define NROWS (Bv*NTIL)     // 544 partial rows
#define NEGW  68            // 17 tiles * 4 words per sentence

typedef unsigned long long u64;
union F2 { u64 u; float2 f; };

__device__ __forceinline__ void fma2(u64 &acc, u64 a, u64 b) {
    asm("fma.rn.f32x2 %0, %1, %2, %0;" : "+l"(acc) : "l"(a), "l"(b));
}
__device__ __forceinline__ u64 dup2(float v) {
    u64 r; asm("mov.b64 %0, {%1,%1};" : "=l"(r) : "f"(v)); return r;
}

// triu row from compacted index p
__device__ __forceinline__ int rowof(int p) {
    int r = (int)((129.0f - sqrtf(16641.0f - 8.0f * (float)p)) * 0.5f);
    if (r < 0) r = 0; if (r > 63) r = 63;
    while (r < 63 && (r + 1) * (129 - (r + 1)) / 2 <= p) r++;
    while (r > 0 && r * (129 - r) / 2 > p) r--;
    return r;
}

// -------- device scratch --------
__device__ float    g_sf[Cc * Sv];      // [c][s] normalized sentence feats
__device__ int      g_scatter[Sv];
__device__ int      g_toppos[Sv];       // argmax-iou flat position
__device__ unsigned g_negw[Sv * NEGW];  // iou>0.5 bits (compacted positions)
__device__ float    g_part[NROWS * Sv];
__device__ float    g_A[Sv * Sv];       // inter-video score matrix

// ============================================================
// K1a (pos 1): scatter idx (tiny serial).
// ============================================================
__global__ void k1a_scatter(const int* __restrict__ num_targets) {
    if (threadIdx.x == 0) {
        int s = 0;
        for (int b = 0; b < Bv && s < Sv; b++) {
            int n = num_targets[b];
            for (int k = 0; k < n && s < Sv; k++) g_scatter[s++] = b;
        }
    }
}

// ============================================================
// K1b (pos 2): normalized sentence feats -> g_sf [c][s].
// ============================================================
__global__ void k1b_sf(const float* __restrict__ sents) {
    int tid = threadIdx.x;               // 128
    int w = tid >> 5, lane = tid & 31;
    for (int s = w; s < Sv; s += 4) {
        float vs[8]; float ss = 0.f;
        #pragma unroll
        for (int k = 0; k < 8; k++) {
            float v = sents[s * Cc + lane + k * 32];
            vs[k] = v; ss += v * v;
        }
        #pragma unroll
        for (int o = 16; o; o >>= 1) ss += __shfl_xor_sync(0xffffffffu, ss, o);
        float rn = 1.f / fmaxf(sqrtf(ss), 1e-12f);
        #pragma unroll
        for (int k = 0; k < 8; k++)
            g_sf[(lane + k * 32) * Sv + s] = vs[k] * rn;
    }
}

// ============================================================
// K1c (pos 3): fused negbits + argmax, ONE pass over iou row.
// ============================================================
__global__ void k1c_ioupass(const float* __restrict__ iou) {
    int s = blockIdx.x;
    int tid = threadIdx.x;      // 128
    int w = tid >> 5, lane = tid & 31;
    __shared__ float sv[128];
    __shared__ int   si[128];

    float bv = -1e30f; int bi = 1 << 30;
    #pragma unroll 1
    for (int k = 0; k < NTIL; k++) {
        int cp = k * 128 + tid;
        bool bit = false;
        if (cp < Pv) {
            int r = rowof(cp);
            int f = r * Nn + r + (cp - r * (129 - r) / 2);
            float v = iou[s * NNv + f];
            bit = v > 0.5f;
            if (v > bv) { bv = v; bi = cp; }   // cp increasing -> lowest kept
        }
        unsigned word = __ballot_sync(0xffffffffu, bit);
        if (lane == 0) g_negw[s * NEGW + 4 * k + w] = word;
    }
    sv[tid] = bv; si[tid] = bi;
    __syncthreads();
    for (int o = 64; o; o >>= 1) {
        if (tid < o) {
            float ov = sv[tid + o]; int oi = si[tid + o];
            if (ov > sv[tid] || (ov == sv[tid] && oi < si[tid])) { sv[tid] = ov; si[tid] = oi; }
        }
        __syncthreads();
    }
    if (tid == 0) {
        int cp = si[0];
        int r = rowof(cp);
        g_toppos[s] = r * Nn + r + (cp - r * (129 - r) / 2);
    }
}

// ============================================================
// K2 (pos 4): fused GEMM + norms + exp/neg partials + A scatter.
//   256 thr, 128-pos tile, thread 8 pos x 4 sentences.
//   acc[4][4] u64 = 64 regs (position-paired f32x2, NO spills).
//   Sentence matrix resident un-dup in smem; dup via 4 movs/cc.
// ============================================================
#define SM_SF   0                        // [256][64] f  = 65536
#define SM_V    65536                    // [2][8][128]  = 8192
#define SM_NRM  (SM_V+8192)              // [256] f      = 1024
#define SM_RN   (SM_NRM+1024)            // [128] f      = 512
#define SM_NEG  (SM_RN+512)              // [64][4] u    = 1024
#define SM_PART (SM_NEG+1024)            // [64][16] f   = 4096
#define SM_SCAT (SM_PART+4096)           // 256
#define SM_TOP  (SM_SCAT+256)            // 256
#define SM_LJ   (SM_TOP+256)             // 256
#define SM_LP   (SM_LJ+256)              // 256
#define SM_CNT  (SM_LP+256)              // 16
#define SM_TOTAL (SM_CNT+16)

__global__ void __launch_bounds__(256, 2)
k2_gemm(const float* __restrict__ V) {
    extern __shared__ __align__(16) char smraw[];
    float*    s_sf   = (float*)(smraw + SM_SF);
    float*    s_v    = (float*)(smraw + SM_V);
    float*    s_nrm  = (float*)(smraw + SM_NRM);
    float*    s_rn   = (float*)(smraw + SM_RN);
    unsigned* s_neg  = (unsigned*)(smraw + SM_NEG);
    float*    s_part = (float*)(smraw + SM_PART);
    int*      s_scat = (int*)(smraw + SM_SCAT);
    int*      s_top  = (int*)(smraw + SM_TOP);
    int*      s_lj   = (int*)(smraw + SM_LJ);
    int*      s_lp   = (int*)(smraw + SM_LP);
    int*      s_cnt  = (int*)(smraw + SM_CNT);

    int tile = blockIdx.x;
    int b    = blockIdx.y;
    int p0   = tile * TP;

    int tid = threadIdx.x;       // 256
    int tx = tid & 15;           // pos group (8 pos)    -> 128 pos
    int ty = tid >> 4;           // sentence group (4 s) -> 64 s
    int lp = tid & 127;          // load position
    int lc = tid >> 7;           // channel parity (0/1)

    int p = p0 + lp;
    int ldf = -1;
    if (p < Pv) {
        int r = rowof(p);
        ldf = r * Nn + r + (p - r * (129 - r) / 2);
    }

    // ---- block fills ----
    for (int i = tid; i < (Cc * Sv) / 4; i += 256)
        ((float4*)s_sf)[i] = ((const float4*)g_sf)[i];
    {
        int s = tid >> 2, w = tid & 3;
        s_neg[tid] = g_negw[s * NEGW + tile * 4 + w];
    }
    if (tid < Sv) { s_scat[tid] = g_scatter[tid]; s_top[tid] = g_toppos[tid]; }
    if (tid == 0) *s_cnt = 0;

    const float* Vb = V + (size_t)b * Cc * NNv;

    float pv[4];
    #pragma unroll
    for (int k = 0; k < 4; k++)
        pv[k] = (ldf >= 0) ? Vb[(2 * k + lc) * NNv + ldf] : 0.f;

    __syncthreads();

    // toplist scan (hidden under prefetch latency)
    if (lc == 0 && ldf >= 0) {
        #pragma unroll 8
        for (int j = 0; j < Sv; j++) {
            if (s_scat[j] == b && s_top[j] == ldf) {
                int idx = atomicAdd(s_cnt, 1);
                s_lj[idx] = j; s_lp[idx] = lp;
            }
        }
    }

    u64 acc[4][4];               // [sentence][pos-pair]: 64 regs total
    #pragma unroll
    for (int si = 0; si < 4; si++)
        #pragma unroll
        for (int q = 0; q < 4; q++) acc[si][q] = 0ull;
    float nrm = 0.f;

    for (int ci = 0; ci < Cc / 8; ci++) {
        int cur = ci & 1;
        #pragma unroll
        for (int k = 0; k < 4; k++) {
            float v = pv[k];
            s_v[(cur * 8 + 2 * k + lc) * TP + lp] = v;
            nrm += v * v;
        }
        __syncthreads();
        if (ci + 1 < Cc / 8) {
            #pragma unroll
            for (int k = 0; k < 4; k++)
                pv[k] = (ldf >= 0) ? Vb[((ci + 1) * 8 + 2 * k + lc) * NNv + ldf] : 0.f;
        }
        #pragma unroll
        for (int cc = 0; cc < 8; cc++) {
            const float* vrow = &s_v[(cur * 8 + cc) * TP + tx * 8];
            ulonglong2 va  = *(const ulonglong2*)(vrow);
            ulonglong2 vb2 = *(const ulonglong2*)(vrow + 4);
            float4 sf4 = *(const float4*)&s_sf[(ci * 8 + cc) * Sv + ty * 4];
            u64 sd0 = dup2(sf4.x), sd1 = dup2(sf4.y);
            u64 sd2 = dup2(sf4.z), sd3 = dup2(sf4.w);
            fma2(acc[0][0], va.x, sd0); fma2(acc[0][1], va.y, sd0);
            fma2(acc[0][2], vb2.x, sd0); fma2(acc[0][3], vb2.y, sd0);
            fma2(acc[1][0], va.x, sd1); fma2(acc[1][1], va.y, sd1);
            fma2(acc[1][2], vb2.x, sd1); fma2(acc[1][3], vb2.y, sd1);
            fma2(acc[2][0], va.x, sd2); fma2(acc[2][1], va.y, sd2);
            fma2(acc[2][2], vb2.x, sd2); fma2(acc[2][3], vb2.y, sd2);
            fma2(acc[3][0], va.x, sd3); fma2(acc[3][1], va.y, sd3);
            fma2(acc[3][2], vb2.x, sd3); fma2(acc[3][3], vb2.y, sd3);
        }
    }

    // column norms: combine the two channel-parity halves
    s_nrm[lc * TP + lp] = nrm;
    __syncthreads();
    if (tid < TP)
        s_rn[tid] = 1.f / fmaxf(sqrtf(s_nrm[tid] + s_nrm[TP + tid]), 1e-12f);
    __syncthreads();

    float rn[8];
    #pragma unroll
    for (int j = 0; j < 8; j++) rn[j] = s_rn[tx * 8 + j];
    int cnt = *s_cnt;

    // epilogue: masked exp partials (4 sentences x 8 pos per thread)
    #pragma unroll
    for (int si = 0; si < 4; si++) {
        int s = ty * 4 + si;
        bool samevid = (s_scat[s] == b);
        unsigned negw = s_neg[s * 4 + (tx >> 2)];
        float part = 0.f;
        #pragma unroll
        for (int q = 0; q < 4; q++) {
            F2 u; u.u = acc[si][q];
            int j0 = 2 * q, j1 = 2 * q + 1;
            int lp0 = tx * 8 + j0, lp1 = tx * 8 + j1;
            bool pos0 = samevid && ((negw >> (lp0 & 31)) & 1u);
            bool pos1 = samevid && ((negw >> (lp1 & 31)) & 1u);
            if ((p0 + lp0) < Pv && !pos0) part += __expf(u.f.x * rn[j0] * 10.0f);
            if ((p0 + lp1) < Pv && !pos1) part += __expf(u.f.y * rn[j1] * 10.0f);
        }
        s_part[s * 16 + tx] = part;
    }

    // inter-video score scatter
    for (int i = 0; i < cnt; i++) {
        int l = s_lp[i];
        if ((l >> 3) == tx) {
            int jj = l & 7, q = jj >> 1, h = jj & 1;
            #pragma unroll
            for (int si = 0; si < 4; si++) {
                F2 u; u.u = acc[si][q];
                float sc = (h ? u.f.y : u.f.x) * rn[jj];
                g_A[s_lj[i] * Sv + ty * 4 + si] = sc;
            }
        }
    }
    __syncthreads();

    if (tid < Sv) {
        float sum = 0.f;
        #pragma unroll
        for (int k = 0; k < 16; k++) sum += s_part[tid * 16 + k];
        g_part[((size_t)b * NTIL + tile) * Sv + tid] = sum;
    }
}

// ============================================================
// K5 (pos 5): final reductions -> two scalar losses. 1024 thr.
// ============================================================
__global__ void k5_final(float* __restrict__ out) {
    __shared__ float sh_lq[64];
    __shared__ float sh_lv[64];
    __shared__ float sh[64];
    int t = threadIdx.x;     // 1024
    int s = t >> 4, k = t & 15;

    float ns = 0.f;
    #pragma unroll 4
    for (int i = k; i < NROWS; i += 16)
        ns += g_part[(size_t)i * Sv + s];
    ns += __shfl_xor_sync(0xffffffffu, ns, 1);
    ns += __shfl_xor_sync(0xffffffffu, ns, 2);
    ns += __shfl_xor_sync(0xffffffffu, ns, 4);
    ns += __shfl_xor_sync(0xffffffffu, ns, 8);
    if (k == 0) {
        float ps = g_A[s * Sv + s];
        float pe = __expf(ps * 10.0f);
        sh_lq[s] = logf(pe + ns) - ps * 10.0f;
    }

    float nsv = 0.f;
    #pragma unroll
    for (int q = 0; q < 4; q++) {
        int u2 = k * 4 + q;
        if (u2 != s) nsv += __expf(g_A[s * Sv + u2] * 10.0f);
    }
    nsv += __shfl_xor_sync(0xffffffffu, nsv, 1);
    nsv += __shfl_xor_sync(0xffffffffu, nsv, 2);
    nsv += __shfl_xor_sync(0xffffffffu, nsv, 4);
    nsv += __shfl_xor_sync(0xffffffffu, nsv, 8);
    if (k == 0) {
        float ps = g_A[s * Sv + s];
        float pe = __expf(ps * 10.0f);
        sh_lv[s] = logf(pe + nsv) - ps * 10.0f;
    }
    __syncthreads();

    if (t < 64) sh[t] = sh_lq[t];
    __syncthreads();
    #pragma unroll
    for (int o = 32; o; o >>= 1) {
        if (t < o) sh[t] += sh[t + o];
        __syncthreads();
    }
    if (t == 0) out[1] = sh[0] / 64.0f;
    __syncthreads();

    if (t < 64) sh[t] = sh_lv[t];
    __syncthreads();
    #pragma unroll
    for (int o = 32; o; o >>= 1) {
        if (t < o) sh[t] += sh[t + o];
        __syncthreads();
    }
    if (t == 0) out[0] = sh[0] / 64.0f;
}

// ============================================================
extern "C" void kernel_launch(void* const* d_in, const int* in_sizes, int n_in,
                              void* d_out, int out_size) {
    const float* video = (const float*)d_in[0];   // [32,256,64,64]
    const float* sents = (const float*)d_in[1];   // [64,256]
    const int*   ntg   = (const int*)  d_in[2];   // [32]
    const float* iou   = (const float*)d_in[3];   // [64,64,64]
    // d_in[4] = mask2d (structural triu; handled analytically)

    cudaFuncSetAttribute(k2_gemm, cudaFuncAttributeMaxDynamicSharedMemorySize,
                         SM_TOTAL);

    k1a_scatter<<<1, 32>>>(ntg);                             // pos 1
    k1b_sf     <<<1, 128>>>(sents);                          // pos 2
    k1c_ioupass<<<Sv, 128>>>(iou);                           // pos 3
    k2_gemm    <<<dim3(NTIL, Bv), 256, SM_TOTAL>>>(video);   // pos 4 (profiled)
    k5_final   <<<1, 1024>>>((float*)d_out);                 // pos 5
}

// round 7
// speedup vs baseline: 3.3638x; 1.5053x over previous
#include <cuda_runtime.h>
#include <cuda_bf16.h>
#include <math.h>

// Problem constants (fixed by setup_inputs)
#define Bv    32
#define Cc    256
#define Nn    64
#define NNv   4096
#define Sv    64
#define Pv    2080          // triu(64x64) count
#define TPn   256           // positions per K2 tile
#define NT    9             // ceil(2080/256)
#define NROWS (Bv*NT)       // 288 partial rows
#define NEGW  72            // words per sentence (65 used + pad)

typedef unsigned long long u64;
union F2 { u64 u; float2 f; };

__device__ __forceinline__ void fma2(u64 &acc, u64 a, u64 b) {
    asm("fma.rn.f32x2 %0, %1, %2, %0;" : "+l"(acc) : "l"(a), "l"(b));
}

// triu row from compacted index p
__device__ __forceinline__ int rowof(int p) {
    int r = (int)((129.0f - sqrtf(16641.0f - 8.0f * (float)p)) * 0.5f);
    if (r < 0) r = 0; if (r > 63) r = 63;
    while (r < 63 && (r + 1) * (129 - (r + 1)) / 2 <= p) r++;
    while (r > 0 && r * (129 - r) / 2 > p) r--;
    return r;
}

// -------- device scratch --------
__device__ float    g_sf[Cc * Sv];      // [c][s] normalized sentence feats
__device__ int      g_scatter[Sv];
__device__ int      g_toppos[Sv];       // argmax-iou flat position
__device__ unsigned g_negw[Sv * NEGW];  // iou>0.5 bits (compacted positions)
__device__ float    g_part[NROWS * Sv];
__device__ float    g_A[Sv * Sv];       // inter-video score matrix

// ============================================================
// K1a (pos 1): scatter idx (tiny serial).
// ============================================================
__global__ void k1a_scatter(const int* __restrict__ num_targets) {
    if (threadIdx.x == 0) {
        int s = 0;
        for (int b = 0; b < Bv && s < Sv; b++) {
            int n = num_targets[b];
            for (int k = 0; k < n && s < Sv; k++) g_scatter[s++] = b;
        }
    }
}

// ============================================================
// K1b (pos 2): normalized sentence feats -> g_sf [c][s].
// ============================================================
__global__ void k1b_sf(const float* __restrict__ sents) {
    int tid = threadIdx.x;               // 128
    int w = tid >> 5, lane = tid & 31;
    for (int s = w; s < Sv; s += 4) {
        float vs[8]; float ss = 0.f;
        #pragma unroll
        for (int k = 0; k < 8; k++) {
            float v = sents[s * Cc + lane + k * 32];
            vs[k] = v; ss += v * v;
        }
        #pragma unroll
        for (int o = 16; o; o >>= 1) ss += __shfl_xor_sync(0xffffffffu, ss, o);
        float rn = 1.f / fmaxf(sqrtf(ss), 1e-12f);
        #pragma unroll
        for (int k = 0; k < 8; k++)
            g_sf[(lane + k * 32) * Sv + s] = vs[k] * rn;
    }
}

// ============================================================
// K1c (pos 3): fused negbits + argmax, ONE pass over iou row.
// ============================================================
__global__ void k1c_ioupass(const float* __restrict__ iou) {
    int s = blockIdx.x;
    int tid = threadIdx.x;      // 128
    int w = tid >> 5, lane = tid & 31;
    __shared__ float sv[128];
    __shared__ int   si[128];

    float bv = -1e30f; int bi = 1 << 30;
    #pragma unroll 1
    for (int k = 0; k < 17; k++) {
        int cp = k * 128 + tid;
        bool bit = false;
        if (cp < Pv) {
            int r = rowof(cp);
            int f = r * Nn + r + (cp - r * (129 - r) / 2);
            float v = iou[s * NNv + f];
            bit = v > 0.5f;
            if (v > bv) { bv = v; bi = cp; }   // cp increasing -> lowest kept
        }
        unsigned word = __ballot_sync(0xffffffffu, bit);
        if (lane == 0) g_negw[s * NEGW + 4 * k + w] = word;
    }
    if (tid < 4) g_negw[s * NEGW + 68 + tid] = 0u;   // pad words
    sv[tid] = bv; si[tid] = bi;
    __syncthreads();
    for (int o = 64; o; o >>= 1) {
        if (tid < o) {
            float ov = sv[tid + o]; int oi = si[tid + o];
            if (ov > sv[tid] || (ov == sv[tid] && oi < si[tid])) { sv[tid] = ov; si[tid] = oi; }
        }
        __syncthreads();
    }
    if (tid == 0) {
        int cp = si[0];
        int r = rowof(cp);
        g_toppos[s] = r * Nn + r + (cp - r * (129 - r) / 2);
    }
}

// ============================================================
// K2 (pos 4): fused GEMM + norms + exp/neg partials + A scatter.
//   256 thr = 8 warps. Tile: 256 pos x 64 s, grid 9x32 = 288
//   blocks = ONE wave. Warp w owns sentences [8w,8w+8); lane l
//   owns positions {4l..4l+3} u {128+4l..128+4l+3} (full-eff
//   LDS.128). acc[4][8] u64 pairs span positions; sentence side
//   comes pre-duplicated from smem (broadcast, zero movs).
// ============================================================
__global__ void __launch_bounds__(256, 2)
k2_gemm(const float* __restrict__ V) {
    __shared__ __align__(16) float s_v[2][8][TPn];     // 16 KB
    __shared__ __align__(16) float s_sfd[2][8][128];   // 8 KB (dup'd sf)
    __shared__ float    s_rn[TPn];
    __shared__ unsigned s_neg[Sv * 8];
    __shared__ int s_scat[Sv], s_top[Sv], s_lj[64], s_lp[64], s_cnt;

    int tile = blockIdx.x;
    int b    = blockIdx.y;
    int p0   = tile * TPn;

    int tid = threadIdx.x;       // 256
    int w = tid >> 5;            // warp: sentences [8w, 8w+8)
    int l = tid & 31;            // lane

    // load position for staging = tid
    int p = p0 + tid;
    int ldf = -1;
    if (p < Pv) {
        int r = rowof(p);
        ldf = r * Nn + r + (p - r * (129 - r) / 2);
    }

    // ---- block fills ----
    s_neg[tid]       = g_negw[(tid >> 3) * NEGW + tile * 8 + (tid & 7)];
    s_neg[tid + 256] = g_negw[((tid + 256) >> 3) * NEGW + tile * 8 + (tid & 7)];
    if (tid < Sv) { s_scat[tid] = g_scatter[tid]; s_top[tid] = g_toppos[tid]; }
    if (tid == 0) s_cnt = 0;

    const float* Vb = V + (size_t)b * Cc * NNv;
    int cc0 = tid >> 6;          // 0..3 (sf staging channel)
    int sI  = tid & 63;          // sf staging sentence

    // prefetch chunk 0
    float pv[8], psf0, psf1;
    #pragma unroll
    for (int k = 0; k < 8; k++)
        pv[k] = (ldf >= 0) ? Vb[k * NNv + ldf] : 0.f;
    psf0 = g_sf[cc0 * Sv + sI];
    psf1 = g_sf[(cc0 + 4) * Sv + sI];

    __syncthreads();   // fills visible

    // toplist scan (hidden under prefetch latency)
    if (ldf >= 0) {
        #pragma unroll 8
        for (int j = 0; j < Sv; j++) {
            if (s_scat[j] == b && s_top[j] == ldf) {
                int idx = atomicAdd(&s_cnt, 1);
                s_lj[idx] = j; s_lp[idx] = tid;
            }
        }
    }

    u64 acc[4][8];               // [pos-pair][sentence]
    #pragma unroll
    for (int q = 0; q < 4; q++)
        #pragma unroll
        for (int s = 0; s < 8; s++) acc[q][s] = 0ull;
    float nrm = 0.f;

    for (int ci = 0; ci < 32; ci++) {
        int cur = ci & 1;
        #pragma unroll
        for (int k = 0; k < 8; k++) {
            float v = pv[k];
            s_v[cur][k][tid] = v;
            nrm += v * v;
        }
        *(float2*)&s_sfd[cur][cc0][2 * sI]     = make_float2(psf0, psf0);
        *(float2*)&s_sfd[cur][cc0 + 4][2 * sI] = make_float2(psf1, psf1);
        __syncthreads();
        if (ci + 1 < 32) {
            #pragma unroll
            for (int k = 0; k < 8; k++)
                pv[k] = (ldf >= 0) ? Vb[((ci + 1) * 8 + k) * NNv + ldf] : 0.f;
            psf0 = g_sf[((ci + 1) * 8 + cc0) * Sv + sI];
            psf1 = g_sf[((ci + 1) * 8 + 4 + cc0) * Sv + sI];
        }
        #pragma unroll
        for (int cc = 0; cc < 8; cc++) {
            ulonglong2 vA = *(const ulonglong2*)&s_v[cur][cc][4 * l];
            ulonglong2 vB = *(const ulonglong2*)&s_v[cur][cc][128 + 4 * l];
            ulonglong2 sA = *(const ulonglong2*)&s_sfd[cur][cc][16 * w];
            ulonglong2 sB = *(const ulonglong2*)&s_sfd[cur][cc][16 * w + 4];
            ulonglong2 sC = *(const ulonglong2*)&s_sfd[cur][cc][16 * w + 8];
            ulonglong2 sD = *(const ulonglong2*)&s_sfd[cur][cc][16 * w + 12];
            u64 sd[8] = {sA.x, sA.y, sB.x, sB.y, sC.x, sC.y, sD.x, sD.y};
            #pragma unroll
            for (int s = 0; s < 8; s++) {
                fma2(acc[0][s], vA.x, sd[s]);
                fma2(acc[1][s], vA.y, sd[s]);
                fma2(acc[2][s], vB.x, sd[s]);
                fma2(acc[3][s], vB.y, sd[s]);
            }
        }
    }

    // column norms (each thread has the full-C norm of position tid)
    s_rn[tid] = 1.f / fmaxf(sqrtf(nrm), 1e-12f);
    __syncthreads();

    // cache inverse norms for this thread's 8 compute positions
    float rnv[8];
    #pragma unroll
    for (int q = 0; q < 4; q++) {
        int bp = (q >> 1) * 128 + 4 * l + (q & 1) * 2;
        rnv[2 * q]     = s_rn[bp];
        rnv[2 * q + 1] = s_rn[bp + 1];
    }
    int cnt = s_cnt;
    int row = b * NT + tile;

    // epilogue: masked exp partials; warp-reduce = full tile sum
    #pragma unroll
    for (int s = 0; s < 8; s++) {
        int sg = 8 * w + s;
        bool samevid = (s_scat[sg] == b);
        unsigned ng0 = s_neg[sg * 8 + (l >> 3)];        // group-0 word
        unsigned ng1 = s_neg[sg * 8 + 4 + (l >> 3)];    // group-1 word
        float part = 0.f;
        #pragma unroll
        for (int q = 0; q < 4; q++) {
            int bp = (q >> 1) * 128 + 4 * l + (q & 1) * 2;
            unsigned ng = (q >> 1) ? ng1 : ng0;
            F2 u; u.u = acc[q][s];
            int lp0 = bp, lp1 = bp + 1;
            bool pos0 = samevid && ((ng >> (lp0 & 31)) & 1u);
            bool pos1 = samevid && ((ng >> (lp1 & 31)) & 1u);
            if ((p0 + lp0) < Pv && !pos0) part += __expf(u.f.x * rnv[2 * q] * 10.0f);
            if ((p0 + lp1) < Pv && !pos1) part += __expf(u.f.y * rnv[2 * q + 1] * 10.0f);
        }
        #pragma unroll
        for (int o = 16; o; o >>= 1) part += __shfl_xor_sync(0xffffffffu, part, o);
        if (l == 0) g_part[(size_t)row * Sv + sg] = part;
    }

    // inter-video score scatter: each warp writes its 8 sentences
    for (int i = 0; i < cnt; i++) {
        int lp = s_lp[i], j = s_lj[i];
        if (((lp & 127) >> 2) == l) {
            int q = ((lp >> 7) << 1) | ((lp >> 1) & 1);
            int h = lp & 1;
            float rr = s_rn[lp];
            #pragma unroll
            for (int s = 0; s < 8; s++) {
                F2 u; u.u = acc[q][s];
                g_A[j * Sv + 8 * w + s] = (h ? u.f.y : u.f.x) * rr;
            }
        }
    }
}

// ============================================================
// K5 (pos 5): final reductions -> two scalar losses. 1024 thr.
// ============================================================
__global__ void k5_final(float* __restrict__ out) {
    __shared__ float sh_lq[64];
    __shared__ float sh_lv[64];
    __shared__ float sh[64];
    int t = threadIdx.x;     // 1024
    int s = t >> 4, k = t & 15;

    float ns = 0.f;
    #pragma unroll 4
    for (int i = k; i < NROWS; i += 16)
        ns += g_part[(size_t)i * Sv + s];
    ns += __shfl_xor_sync(0xffffffffu, ns, 1);
    ns += __shfl_xor_sync(0xffffffffu, ns, 2);
    ns += __shfl_xor_sync(0xffffffffu, ns, 4);
    ns += __shfl_xor_sync(0xffffffffu, ns, 8);
    if (k == 0) {
        float ps = g_A[s * Sv + s];
        float pe = __expf(ps * 10.0f);
        sh_lq[s] = logf(pe + ns) - ps * 10.0f;
    }

    float nsv = 0.f;
    #pragma unroll
    for (int q = 0; q < 4; q++) {
        int u2 = k * 4 + q;
        if (u2 != s) nsv += __expf(g_A[s * Sv + u2] * 10.0f);
    }
    nsv += __shfl_xor_sync(0xffffffffu, nsv, 1);
    nsv += __shfl_xor_sync(0xffffffffu, nsv, 2);
    nsv += __shfl_xor_sync(0xffffffffu, nsv, 4);
    nsv += __shfl_xor_sync(0xffffffffu, nsv, 8);
    if (k == 0) {
        float ps = g_A[s * Sv + s];
        float pe = __expf(ps * 10.0f);
        sh_lv[s] = logf(pe + nsv) - ps * 10.0f;
    }
    __syncthreads();

    if (t < 64) sh[t] = sh_lq[t];
    __syncthreads();
    #pragma unroll
    for (int o = 32; o; o >>= 1) {
        if (t < o) sh[t] += sh[t + o];
        __syncthreads();
    }
    if (t == 0) out[1] = sh[0] / 64.0f;
    __syncthreads();

    if (t < 64) sh[t] = sh_lv[t];
    __syncthreads();
    #pragma unroll
    for (int o = 32; o; o >>= 1) {
        if (t < o) sh[t] += sh[t + o];
        __syncthreads();
    }
    if (t == 0) out[0] = sh[0] / 64.0f;
}

// ============================================================
extern "C" void kernel_launch(void* const* d_in, const int* in_sizes, int n_in,
                              void* d_out, int out_size) {
    const float* video = (const float*)d_in[0];   // [32,256,64,64]
    const float* sents = (const float*)d_in[1];   // [64,256]
    const int*   ntg   = (const int*)  d_in[2];   // [32]
    const float* iou   = (const float*)d_in[3];   // [64,64,64]
    // d_in[4] = mask2d (structural triu; handled analytically)

    k1a_scatter<<<1, 32>>>(ntg);                           // pos 1
    k1b_sf     <<<1, 128>>>(sents);                        // pos 2
    k1c_ioupass<<<Sv, 128>>>(iou);                         // pos 3
    k2_gemm    <<<dim3(NT, Bv), 256>>>(video);             // pos 4 (profiled)
    k5_final   <<<1, 1024>>>((float*)d_out);               // pos 5
}

// round 9
// speedup vs baseline: 4.0625x; 1.2077x over previous
#include <cuda_runtime.h>
#include <cuda_bf16.h>
#include <math.h>

// Problem constants (fixed by setup_inputs)
#define Bv    32
#define Cc    256
#define Nn    64
#define NNv   4096
#define Sv    64
#define Pv    2080          // triu(64x64) count
#define TP    128           // positions per K2 tile
#define NT    17            // ceil(2080/128)
#define NROWS (Bv*NT)       // 544 partial rows
#define NEGW  68            // 17 tiles * 4 words per sentence

typedef unsigned long long u64;
union F2 { u64 u; float2 f; };

__device__ __forceinline__ void fma2(u64 &acc, u64 a, u64 b) {
    asm("fma.rn.f32x2 %0, %1, %2, %0;" : "+l"(acc) : "l"(a), "l"(b));
}

// triu row from compacted index p
__device__ __forceinline__ int rowof(int p) {
    int r = (int)((129.0f - sqrtf(16641.0f - 8.0f * (float)p)) * 0.5f);
    if (r < 0) r = 0; if (r > 63) r = 63;
    while (r < 63 && (r + 1) * (129 - (r + 1)) / 2 <= p) r++;
    while (r > 0 && r * (129 - r) / 2 > p) r--;
    return r;
}

// -------- device scratch --------
__device__ float    g_sf[Cc * Sv];      // [c][s] normalized sentence feats
__device__ int      g_scatter[Sv];
__device__ int      g_toppos[Sv];       // argmax-iou flat position
__device__ unsigned g_negw[Sv * NEGW];  // iou>0.5 bits (compacted positions)
__device__ float    g_part[NROWS * Sv];
__device__ float    g_A[Sv * Sv];       // inter-video score matrix

// ============================================================
// K1a (pos 1): scatter idx (tiny serial).
// ============================================================
__global__ void k1a_scatter(const int* __restrict__ num_targets) {
    if (threadIdx.x == 0) {
        int s = 0;
        for (int b = 0; b < Bv && s < Sv; b++) {
            int n = num_targets[b];
            for (int k = 0; k < n && s < Sv; k++) g_scatter[s++] = b;
        }
    }
}

// ============================================================
// K1b (pos 2): normalized sentence feats -> g_sf [c][s].
// ============================================================
__global__ void k1b_sf(const float* __restrict__ sents) {
    int tid = threadIdx.x;               // 128
    int w = tid >> 5, lane = tid & 31;
    for (int s = w; s < Sv; s += 4) {
        float vs[8]; float ss = 0.f;
        #pragma unroll
        for (int k = 0; k < 8; k++) {
            float v = sents[s * Cc + lane + k * 32];
            vs[k] = v; ss += v * v;
        }
        #pragma unroll
        for (int o = 16; o; o >>= 1) ss += __shfl_xor_sync(0xffffffffu, ss, o);
        float rn = 1.f / fmaxf(sqrtf(ss), 1e-12f);
        #pragma unroll
        for (int k = 0; k < 8; k++)
            g_sf[(lane + k * 32) * Sv + s] = vs[k] * rn;
    }
}

// ============================================================
// K1c (pos 3): fused negbits + argmax, ONE pass over iou row.
// ============================================================
__global__ void k1c_ioupass(const float* __restrict__ iou) {
    int s = blockIdx.x;
    int tid = threadIdx.x;      // 128
    int w = tid >> 5, lane = tid & 31;
    __shared__ float sv[128];
    __shared__ int   si[128];

    float bv = -1e30f; int bi = 1 << 30;
    #pragma unroll 1
    for (int k = 0; k < NT; k++) {
        int cp = k * 128 + tid;
        bool bit = false;
        if (cp < Pv) {
            int r = rowof(cp);
            int f = r * Nn + r + (cp - r * (129 - r) / 2);
            float v = iou[s * NNv + f];
            bit = v > 0.5f;
            if (v > bv) { bv = v; bi = cp; }   // cp increasing -> lowest kept
        }
        unsigned word = __ballot_sync(0xffffffffu, bit);
        if (lane == 0) g_negw[s * NEGW + 4 * k + w] = word;
    }
    sv[tid] = bv; si[tid] = bi;
    __syncthreads();
    for (int o = 64; o; o >>= 1) {
        if (tid < o) {
            float ov = sv[tid + o]; int oi = si[tid + o];
            if (ov > sv[tid] || (ov == sv[tid] && oi < si[tid])) { sv[tid] = ov; si[tid] = oi; }
        }
        __syncthreads();
    }
    if (tid == 0) {
        int cp = si[0];
        int r = rowof(cp);
        g_toppos[s] = r * Nn + r + (cp - r * (129 - r) / 2);
    }
}

// ============================================================
// K2 (pos 4): fused GEMM + norms + exp/neg partials + A scatter.
//   256 thr = 8 warps, tile 128 pos x 64 s, grid 17x32.
//   Warp w owns sentences [8w,8w+8); lane l owns positions
//   4l..4l+3 (one full-efficiency LDS.128). acc[2][8] u64 =
//   32 regs -> NO spills. sf pre-duplicated in smem (broadcast
//   LDS, zero movs).
// ============================================================
__global__ void __launch_bounds__(256, 2)
k2_gemm(const float* __restrict__ V) {
    __shared__ __align__(16) float s_v[2][8][TP];      // 8 KB
    __shared__ __align__(16) float s_sfd[2][8][128];   // 8 KB (dup'd sf)
    __shared__ float    s_nrm[256];
    __shared__ float    s_rn[TP];
    __shared__ unsigned s_neg[Sv * 4];
    __shared__ int s_scat[Sv], s_top[Sv], s_lj[64], s_lp[64], s_cnt;

    int tile = blockIdx.x;
    int b    = blockIdx.y;
    int p0   = tile * TP;

    int tid = threadIdx.x;       // 256
    int w = tid >> 5;            // warp: sentences [8w, 8w+8)
    int l = tid & 31;            // lane: positions 4l..4l+3

    // staging role
    int lp = tid & 127;          // staged position
    int lc = tid >> 7;           // channel parity (0/1)
    int p = p0 + lp;
    int ldf = -1;
    if (p < Pv) {
        int r = rowof(p);
        ldf = r * Nn + r + (p - r * (129 - r) / 2);
    }

    // ---- block fills ----
    s_neg[tid] = g_negw[(tid >> 2) * NEGW + tile * 4 + (tid & 3)];
    if (tid < Sv) { s_scat[tid] = g_scatter[tid]; s_top[tid] = g_toppos[tid]; }
    if (tid == 0) s_cnt = 0;

    const float* Vb = V + (size_t)b * Cc * NNv;
    int cc0 = tid >> 6;          // 0..3 (sf staging channel)
    int sI  = tid & 63;          // sf staging sentence

    // prefetch chunk 0
    float pv[4], psf0, psf1;
    #pragma unroll
    for (int k = 0; k < 4; k++)
        pv[k] = (ldf >= 0) ? Vb[(2 * k + lc) * NNv + ldf] : 0.f;
    psf0 = g_sf[cc0 * Sv + sI];
    psf1 = g_sf[(cc0 + 4) * Sv + sI];

    __syncthreads();   // fills visible

    // toplist scan (hidden under prefetch latency)
    if (lc == 0 && ldf >= 0) {
        #pragma unroll 8
        for (int j = 0; j < Sv; j++) {
            if (s_scat[j] == b && s_top[j] == ldf) {
                int idx = atomicAdd(&s_cnt, 1);
                s_lj[idx] = j; s_lp[idx] = lp;
            }
        }
    }

    u64 acc[2][8];               // [pos-pair][sentence] = 32 regs
    #pragma unroll
    for (int q = 0; q < 2; q++)
        #pragma unroll
        for (int s = 0; s < 8; s++) acc[q][s] = 0ull;
    float nrm = 0.f;

    for (int ci = 0; ci < 32; ci++) {
        int cur = ci & 1;
        #pragma unroll
        for (int k = 0; k < 4; k++) {
            float v = pv[k];
            s_v[cur][2 * k + lc][lp] = v;
            nrm += v * v;
        }
        *(float2*)&s_sfd[cur][cc0][2 * sI]     = make_float2(psf0, psf0);
        *(float2*)&s_sfd[cur][cc0 + 4][2 * sI] = make_float2(psf1, psf1);
        __syncthreads();
        if (ci + 1 < 32) {
            #pragma unroll
            for (int k = 0; k < 4; k++)
                pv[k] = (ldf >= 0) ? Vb[((ci + 1) * 8 + 2 * k + lc) * NNv + ldf] : 0.f;
            psf0 = g_sf[((ci + 1) * 8 + cc0) * Sv + sI];
            psf1 = g_sf[((ci + 1) * 8 + 4 + cc0) * Sv + sI];
        }
        #pragma unroll
        for (int cc = 0; cc < 8; cc++) {
            ulonglong2 vA = *(const ulonglong2*)&s_v[cur][cc][4 * l];
            ulonglong2 sA = *(const ulonglong2*)&s_sfd[cur][cc][16 * w];
            ulonglong2 sB = *(const ulonglong2*)&s_sfd[cur][cc][16 * w + 4];
            ulonglong2 sC = *(const ulonglong2*)&s_sfd[cur][cc][16 * w + 8];
            ulonglong2 sD = *(const ulonglong2*)&s_sfd[cur][cc][16 * w + 12];
            u64 sd[8] = {sA.x, sA.y, sB.x, sB.y, sC.x, sC.y, sD.x, sD.y};
            #pragma unroll
            for (int s = 0; s < 8; s++) {
                fma2(acc[0][s], vA.x, sd[s]);
                fma2(acc[1][s], vA.y, sd[s]);
            }
        }
    }

    // column norms: combine the two channel-parity halves
    s_nrm[lc * TP + lp] = nrm;
    __syncthreads();
    if (tid < TP)
        s_rn[tid] = 1.f / fmaxf(sqrtf(s_nrm[tid] + s_nrm[TP + tid]), 1e-12f);
    __syncthreads();

    float rn0 = s_rn[4 * l],     rn1 = s_rn[4 * l + 1];
    float rn2 = s_rn[4 * l + 2], rn3 = s_rn[4 * l + 3];
    int cnt = s_cnt;
    int row = b * NT + tile;
    bool v0 = (p0 + 4 * l)     < Pv, v1 = (p0 + 4 * l + 1) < Pv;
    bool v2 = (p0 + 4 * l + 2) < Pv, v3 = (p0 + 4 * l + 3) < Pv;
    int shift = (4 * l) & 31;    // bits for positions 4l..4l+3 (same word)

    // epilogue: masked exp partials; warp covers all 128 positions
    #pragma unroll
    for (int s = 0; s < 8; s++) {
        int sg = 8 * w + s;
        bool samevid = (s_scat[sg] == b);
        unsigned ng = samevid ? (s_neg[sg * 4 + (l >> 3)] >> shift) : 0u;
        F2 u0; u0.u = acc[0][s];
        F2 u1; u1.u = acc[1][s];
        float part = 0.f;
        if (v0 && !(ng & 1u)) part += __expf(u0.f.x * rn0 * 10.0f);
        if (v1 && !(ng & 2u)) part += __expf(u0.f.y * rn1 * 10.0f);
        if (v2 && !(ng & 4u)) part += __expf(u1.f.x * rn2 * 10.0f);
        if (v3 && !(ng & 8u)) part += __expf(u1.f.y * rn3 * 10.0f);
        #pragma unroll
        for (int o = 16; o; o >>= 1) part += __shfl_xor_sync(0xffffffffu, part, o);
        if (l == 0) g_part[(size_t)row * Sv + sg] = part;
    }

    // inter-video score scatter: each warp writes its 8 sentences
    for (int i = 0; i < cnt; i++) {
        int tp2 = s_lp[i], j = s_lj[i];
        if ((tp2 >> 2) == l) {
            int q = (tp2 >> 1) & 1;
            int h = tp2 & 1;
            float rr = s_rn[tp2];
            #pragma unroll
            for (int s = 0; s < 8; s++) {
                F2 u; u.u = acc[q][s];
                g_A[j * Sv + 8 * w + s] = (h ? u.f.y : u.f.x) * rr;
            }
        }
    }
}

// ============================================================
// K5 (pos 5): final reductions -> two scalar losses. 1024 thr.
// ============================================================
__global__ void k5_final(float* __restrict__ out) {
    __shared__ float sh_lq[64];
    __shared__ float sh_lv[64];
    __shared__ float sh[64];
    int t = threadIdx.x;     // 1024
    int s = t >> 4, k = t & 15;

    float ns = 0.f;
    #pragma unroll 4
    for (int i = k; i < NROWS; i += 16)
        ns += g_part[(size_t)i * Sv + s];
    ns += __shfl_xor_sync(0xffffffffu, ns, 1);
    ns += __shfl_xor_sync(0xffffffffu, ns, 2);
    ns += __shfl_xor_sync(0xffffffffu, ns, 4);
    ns += __shfl_xor_sync(0xffffffffu, ns, 8);
    if (k == 0) {
        float ps = g_A[s * Sv + s];
        float pe = __expf(ps * 10.0f);
        sh_lq[s] = logf(pe + ns) - ps * 10.0f;
    }

    float nsv = 0.f;
    #pragma unroll
    for (int q = 0; q < 4; q++) {
        int u2 = k * 4 + q;
        if (u2 != s) nsv += __expf(g_A[s * Sv + u2] * 10.0f);
    }
    nsv += __shfl_xor_sync(0xffffffffu, nsv, 1);
    nsv += __shfl_xor_sync(0xffffffffu, nsv, 2);
    nsv += __shfl_xor_sync(0xffffffffu, nsv, 4);
    nsv += __shfl_xor_sync(0xffffffffu, nsv, 8);
    if (k == 0) {
        float ps = g_A[s * Sv + s];
        float pe = __expf(ps * 10.0f);
        sh_lv[s] = logf(pe + nsv) - ps * 10.0f;
    }
    __syncthreads();

    if (t < 64) sh[t] = sh_lq[t];
    __syncthreads();
    #pragma unroll
    for (int o = 32; o; o >>= 1) {
        if (t < o) sh[t] += sh[t + o];
        __syncthreads();
    }
    if (t == 0) out[1] = sh[0] / 64.0f;
    __syncthreads();

    if (t < 64) sh[t] = sh_lv[t];
    __syncthreads();
    #pragma unroll
    for (int o = 32; o; o >>= 1) {
        if (t < o) sh[t] += sh[t + o];
        __syncthreads();
    }
    if (t == 0) out[0] = sh[0] / 64.0f;
}

// ============================================================
extern "C" void kernel_launch(void* const* d_in, const int* in_sizes, int n_in,
                              void* d_out, int out_size) {
    const float* video = (const float*)d_in[0];   // [32,256,64,64]
    const float* sents = (const float*)d_in[1];   // [64,256]
    const int*   ntg   = (const int*)  d_in[2];   // [32]
    const float* iou   = (const float*)d_in[3];   // [64,64,64]
    // d_in[4] = mask2d (structural triu; handled analytically)

    k1a_scatter<<<1, 32>>>(ntg);                           // pos 1
    k1b_sf     <<<1, 128>>>(sents);                        // pos 2
    k1c_ioupass<<<Sv, 128>>>(iou);                         // pos 3
    k2_gemm    <<<dim3(NT, Bv), 256>>>(video);             // pos 4 (profiled)
    k5_final   <<<1, 1024>>>((float*)d_out);               // pos 5
}

// round 10
// speedup vs baseline: 4.8124x; 1.1846x over previous
#include <cuda_runtime.h>
#include <cuda_bf16.h>
#include <math.h>

// Problem constants (fixed by setup_inputs)
#define Bv    32
#define Cc    256
#define Nn    64
#define NNv   4096
#define Sv    64
#define Pv    2080          // triu(64x64) count
#define TP    128           // positions per K2 tile
#define NT    17            // ceil(2080/128)
#define NROWS (Bv*NT)       // 544 partial rows
#define NEGW  68            // 17 tiles * 4 words per sentence

typedef unsigned long long u64;
union F2 { u64 u; float2 f; };

__device__ __forceinline__ void fma2(u64 &acc, u64 a, u64 b) {
    asm("fma.rn.f32x2 %0, %1, %2, %0;" : "+l"(acc) : "l"(a), "l"(b));
}
__device__ __forceinline__ unsigned sm_u32(const void* p) {
    return (unsigned)__cvta_generic_to_shared(p);
}
__device__ __forceinline__ void cp4(unsigned dst, const float* src, int zf) {
    asm volatile("cp.async.ca.shared.global [%0], [%1], 4, %2;"
                 :: "r"(dst), "l"(src), "r"(zf));
}
__device__ __forceinline__ void cp16(unsigned dst, const float* src) {
    asm volatile("cp.async.cg.shared.global [%0], [%1], 16;"
                 :: "r"(dst), "l"(src));
}
__device__ __forceinline__ void cp_commit() {
    asm volatile("cp.async.commit_group;" ::: "memory");
}
__device__ __forceinline__ void cp_wait1() {
    asm volatile("cp.async.wait_group 1;" ::: "memory");
}
__device__ __forceinline__ void cp_wait0() {
    asm volatile("cp.async.wait_group 0;" ::: "memory");
}

// triu row from compacted index p
__device__ __forceinline__ int rowof(int p) {
    int r = (int)((129.0f - sqrtf(16641.0f - 8.0f * (float)p)) * 0.5f);
    if (r < 0) r = 0; if (r > 63) r = 63;
    while (r < 63 && (r + 1) * (129 - (r + 1)) / 2 <= p) r++;
    while (r > 0 && r * (129 - r) / 2 > p) r--;
    return r;
}

// -------- device scratch --------
__device__ __align__(16) float g_sfd[Cc * 128];   // [c][2s] duplicated normalized sf
__device__ int      g_scatter[Sv];
__device__ int      g_toppos[Sv];
__device__ unsigned g_negw[Sv * NEGW];
__device__ float    g_part[NROWS * Sv];
__device__ float    g_A[Sv * Sv];
__device__ float    g_lq[Sv], g_lv[Sv];

// ============================================================
// K1a (pos 1): scatter idx (tiny serial).
// ============================================================
__global__ void k1a_scatter(const int* __restrict__ num_targets) {
    if (threadIdx.x == 0) {
        int s = 0;
        for (int b = 0; b < Bv && s < Sv; b++) {
            int n = num_targets[b];
            for (int k = 0; k < n && s < Sv; k++) g_scatter[s++] = b;
        }
    }
}

// ============================================================
// K1b (pos 2): normalized sentence feats -> g_sfd [c][2s] dup.
// ============================================================
__global__ void k1b_sf(const float* __restrict__ sents) {
    int tid = threadIdx.x;               // 128
    int w = tid >> 5, lane = tid & 31;
    for (int s = w; s < Sv; s += 4) {
        float vs[8]; float ss = 0.f;
        #pragma unroll
        for (int k = 0; k < 8; k++) {
            float v = sents[s * Cc + lane + k * 32];
            vs[k] = v; ss += v * v;
        }
        #pragma unroll
        for (int o = 16; o; o >>= 1) ss += __shfl_xor_sync(0xffffffffu, ss, o);
        float rn = 1.f / fmaxf(sqrtf(ss), 1e-12f);
        #pragma unroll
        for (int k = 0; k < 8; k++) {
            float v = vs[k] * rn;
            int c = lane + k * 32;
            g_sfd[c * 128 + 2 * s]     = v;
            g_sfd[c * 128 + 2 * s + 1] = v;
        }
    }
}

// ============================================================
// K1c (pos 3): fused negbits + argmax, ONE pass over iou row.
// ============================================================
__global__ void k1c_ioupass(const float* __restrict__ iou) {
    int s = blockIdx.x;
    int tid = threadIdx.x;      // 128
    int w = tid >> 5, lane = tid & 31;
    __shared__ float sv[128];
    __shared__ int   si[128];

    float bv = -1e30f; int bi = 1 << 30;
    #pragma unroll 1
    for (int k = 0; k < NT; k++) {
        int cp = k * 128 + tid;
        bool bit = false;
        if (cp < Pv) {
            int r = rowof(cp);
            int f = r * Nn + r + (cp - r * (129 - r) / 2);
            float v = iou[s * NNv + f];
            bit = v > 0.5f;
            if (v > bv) { bv = v; bi = cp; }
        }
        unsigned word = __ballot_sync(0xffffffffu, bit);
        if (lane == 0) g_negw[s * NEGW + 4 * k + w] = word;
    }
    sv[tid] = bv; si[tid] = bi;
    __syncthreads();
    for (int o = 64; o; o >>= 1) {
        if (tid < o) {
            float ov = sv[tid + o]; int oi = si[tid + o];
            if (ov > sv[tid] || (ov == sv[tid] && oi < si[tid])) { sv[tid] = ov; si[tid] = oi; }
        }
        __syncthreads();
    }
    if (tid == 0) {
        int cp = si[0];
        int r = rowof(cp);
        g_toppos[s] = r * Nn + r + (cp - r * (129 - r) / 2);
    }
}

// ============================================================
// K2 (pos 4): fused GEMM + norms + exp/neg partials + A scatter.
//   256 thr = 8 warps, tile 128 pos x 64 s, grid 17x32.
//   cp.async double-buffer staging (no STS, no prefetch regs).
//   acc[2][8] u64 = 32 regs. Norms: warp w handles cc==w slice.
//   3 blocks/SM target.
// ============================================================
__global__ void __launch_bounds__(256, 3)
k2_gemm(const float* __restrict__ V) {
    __shared__ __align__(16) float s_v[2][8][TP];      // 4KB x2
    __shared__ __align__(16) float s_sfd[2][1024];     // 4KB x2 (dup'd sf chunk)
    __shared__ float    s_rn[TP];
    __shared__ unsigned s_neg[Sv * 4];
    __shared__ int s_scat[Sv], s_top[Sv], s_lj[64], s_lp[64], s_cnt;

    int tile = blockIdx.x;
    int b    = blockIdx.y;
    int p0   = tile * TP;

    int tid = threadIdx.x;       // 256
    int w = tid >> 5;            // warp: sentences [8w, 8w+8)
    int l = tid & 31;            // lane: positions 4l..4l+3

    int lp = tid & 127;          // staged position
    int lc = tid >> 7;           // channel parity (0/1)
    int p = p0 + lp;
    int ldf = 0, zf = 0;
    if (p < Pv) {
        int r = rowof(p);
        ldf = r * Nn + r + (p - r * (129 - r) / 2);
        zf = 4;
    }

    // ---- block fills ----
    s_neg[tid] = g_negw[(tid >> 2) * NEGW + tile * 4 + (tid & 3)];
    if (tid < Sv) { s_scat[tid] = g_scatter[tid]; s_top[tid] = g_toppos[tid]; }
    if (tid == 0) s_cnt = 0;

    const float* Vb = V + (size_t)b * Cc * NNv + ldf;
    unsigned svb = sm_u32(&s_v[0][0][0]);
    unsigned sfb = sm_u32(&s_sfd[0][0]);

    // prologue: stage chunks 0 and 1
    #pragma unroll
    for (int st = 0; st < 2; st++) {
        #pragma unroll
        for (int k = 0; k < 4; k++) {
            int cc = 2 * k + lc;
            cp4(svb + (((unsigned)st * 1024u) + cc * TP + lp) * 4u,
                Vb + (size_t)(st * 8 + cc) * NNv, zf);
        }
        cp16(sfb + ((unsigned)st * 1024u + tid * 4u) * 4u,
             g_sfd + st * 1024 + tid * 4);
        cp_commit();
    }
    __syncthreads();   // s_scat/s_top visible

    // toplist scan (hidden under cp.async latency)
    if (lc == 0 && zf) {
        #pragma unroll 8
        for (int j = 0; j < Sv; j++) {
            if (s_scat[j] == b && s_top[j] == ldf) {
                int idx = atomicAdd(&s_cnt, 1);
                s_lj[idx] = j; s_lp[idx] = lp;
            }
        }
    }

    u64 acc[2][8];               // [pos-pair][sentence] = 32 regs
    #pragma unroll
    for (int q = 0; q < 2; q++)
        #pragma unroll
        for (int s = 0; s < 8; s++) acc[q][s] = 0ull;
    u64 nacc0 = 0ull, nacc1 = 0ull;   // this warp's cc-slice norms

    #pragma unroll 1
    for (int ci = 0; ci < 32; ci++) {
        int cur = ci & 1;
        if (ci == 31) cp_wait0(); else cp_wait1();
        __syncthreads();
        #pragma unroll
        for (int cc = 0; cc < 8; cc++) {
            ulonglong2 vA = *(const ulonglong2*)&s_v[cur][cc][4 * l];
            ulonglong2 sA = *(const ulonglong2*)&s_sfd[cur][cc * 128 + 16 * w];
            ulonglong2 sB = *(const ulonglong2*)&s_sfd[cur][cc * 128 + 16 * w + 4];
            ulonglong2 sC = *(const ulonglong2*)&s_sfd[cur][cc * 128 + 16 * w + 8];
            ulonglong2 sD = *(const ulonglong2*)&s_sfd[cur][cc * 128 + 16 * w + 12];
            u64 sd[8] = {sA.x, sA.y, sB.x, sB.y, sC.x, sC.y, sD.x, sD.y};
            #pragma unroll
            for (int s = 0; s < 8; s++) {
                fma2(acc[0][s], vA.x, sd[s]);
                fma2(acc[1][s], vA.y, sd[s]);
            }
            if (cc == w) {       // balanced norm slice: warp w owns cc==w
                fma2(nacc0, vA.x, vA.x);
                fma2(nacc1, vA.y, vA.y);
            }
        }
        __syncthreads();         // all warps done reading buffer `cur`
        if (ci + 2 < 32) {       // stage chunk ci+2 into buffer `cur`
            #pragma unroll
            for (int k = 0; k < 4; k++) {
                int cc = 2 * k + lc;
                cp4(svb + (((unsigned)cur * 1024u) + cc * TP + lp) * 4u,
                    Vb + (size_t)((ci + 2) * 8 + cc) * NNv, zf);
            }
            cp16(sfb + ((unsigned)cur * 1024u + tid * 4u) * 4u,
                 g_sfd + (ci + 2) * 1024 + tid * 4);
            cp_commit();
        }
    }

    // cross-warp norm reduction (reuse s_v[0] as [8][128] scratch)
    float* s_nrmp = &s_v[0][0][0];
    {
        F2 u0; u0.u = nacc0;
        F2 u1; u1.u = nacc1;
        s_nrmp[w * TP + 4 * l]     = u0.f.x;
        s_nrmp[w * TP + 4 * l + 1] = u0.f.y;
        s_nrmp[w * TP + 4 * l + 2] = u1.f.x;
        s_nrmp[w * TP + 4 * l + 3] = u1.f.y;
    }
    __syncthreads();
    if (tid < TP) {
        float nr = 0.f;
        #pragma unroll
        for (int ww = 0; ww < 8; ww++) nr += s_nrmp[ww * TP + tid];
        s_rn[tid] = 1.f / fmaxf(sqrtf(nr), 1e-12f);
    }
    __syncthreads();

    float rn0 = s_rn[4 * l],     rn1 = s_rn[4 * l + 1];
    float rn2 = s_rn[4 * l + 2], rn3 = s_rn[4 * l + 3];
    int cnt = s_cnt;
    int row = b * NT + tile;
    bool v0 = (p0 + 4 * l)     < Pv, v1 = (p0 + 4 * l + 1) < Pv;
    bool v2 = (p0 + 4 * l + 2) < Pv, v3 = (p0 + 4 * l + 3) < Pv;
    int shift = (4 * l) & 31;

    // epilogue: masked exp partials; warp covers all 128 positions
    #pragma unroll
    for (int s = 0; s < 8; s++) {
        int sg = 8 * w + s;
        bool samevid = (s_scat[sg] == b);
        unsigned ng = samevid ? (s_neg[sg * 4 + (l >> 3)] >> shift) : 0u;
        F2 u0; u0.u = acc[0][s];
        F2 u1; u1.u = acc[1][s];
        float part = 0.f;
        if (v0 && !(ng & 1u)) part += __expf(u0.f.x * rn0 * 10.0f);
        if (v1 && !(ng & 2u)) part += __expf(u0.f.y * rn1 * 10.0f);
        if (v2 && !(ng & 4u)) part += __expf(u1.f.x * rn2 * 10.0f);
        if (v3 && !(ng & 8u)) part += __expf(u1.f.y * rn3 * 10.0f);
        #pragma unroll
        for (int o = 16; o; o >>= 1) part += __shfl_xor_sync(0xffffffffu, part, o);
        if (l == 0) g_part[(size_t)row * Sv + sg] = part;
    }

    // inter-video score scatter
    for (int i = 0; i < cnt; i++) {
        int tp2 = s_lp[i], j = s_lj[i];
        if ((tp2 >> 2) == l) {
            int q = (tp2 >> 1) & 1;
            int h = tp2 & 1;
            float rr = s_rn[tp2];
            #pragma unroll
            for (int s = 0; s < 8; s++) {
                F2 u; u.u = acc[q][s];
                g_A[j * Sv + 8 * w + s] = (h ? u.f.y : u.f.x) * rr;
            }
        }
    }
}

// ============================================================
// K5a (pos 5): per-sentence losses (grid 64).
// ============================================================
__global__ void k5a_persent(float* __restrict__ dummy) {
    int s = blockIdx.x;
    int t = threadIdx.x;     // 128
    __shared__ float red[128];

    float ns = 0.f;
    #pragma unroll 5
    for (int i = t; i < NROWS; i += 128)
        ns += g_part[(size_t)i * Sv + s];
    red[t] = ns;
    __syncthreads();
    for (int o = 64; o; o >>= 1) {
        if (t < o) red[t] += red[t + o];
        __syncthreads();
    }
    float nst = red[0];
    __syncthreads();

    float ev = 0.f;
    if (t < Sv && t != s) ev = __expf(g_A[s * Sv + t] * 10.0f);
    red[t] = ev;
    __syncthreads();
    for (int o = 64; o; o >>= 1) {
        if (t < o) red[t] += red[t + o];
        __syncthreads();
    }
    if (t == 0) {
        float ps = g_A[s * Sv + s];
        float pe = __expf(ps * 10.0f);
        g_lq[s] = logf(pe + nst)   - ps * 10.0f;
        g_lv[s] = logf(pe + red[0]) - ps * 10.0f;
    }
}

// ============================================================
// K5b (pos 6): final means -> out[0], out[1].
// ============================================================
__global__ void k5b_final(float* __restrict__ out) {
    __shared__ float sh[64];
    int t = threadIdx.x;     // 64

    sh[t] = g_lq[t];
    __syncthreads();
    #pragma unroll
    for (int o = 32; o; o >>= 1) {
        if (t < o) sh[t] += sh[t + o];
        __syncthreads();
    }
    if (t == 0) out[1] = sh[0] / 64.0f;
    __syncthreads();

    sh[t] = g_lv[t];
    __syncthreads();
    #pragma unroll
    for (int o = 32; o; o >>= 1) {
        if (t < o) sh[t] += sh[t + o];
        __syncthreads();
    }
    if (t == 0) out[0] = sh[0] / 64.0f;
}

// ============================================================
extern "C" void kernel_launch(void* const* d_in, const int* in_sizes, int n_in,
                              void* d_out, int out_size) {
    const float* video = (const float*)d_in[0];   // [32,256,64,64]
    const float* sents = (const float*)d_in[1];   // [64,256]
    const int*   ntg   = (const int*)  d_in[2];   // [32]
    const float* iou   = (const float*)d_in[3];   // [64,64,64]
    // d_in[4] = mask2d (structural triu; handled analytically)

    k1a_scatter<<<1, 32>>>(ntg);                           // pos 1
    k1b_sf     <<<1, 128>>>(sents);                        // pos 2
    k1c_ioupass<<<Sv, 128>>>(iou);                         // pos 3
    k2_gemm    <<<dim3(NT, Bv), 256>>>(video);             // pos 4 (profiled)
    k5a_persent<<<Sv, 128>>>((float*)d_out);               // pos 5
    k5b_final  <<<1, 64>>>((float*)d_out);                 // pos 6
}